// round 1
// baseline (speedup 1.0000x reference)
#include <cuda_runtime.h>
#include <cuda_bf16.h>

#define BATCH 128
#define CH    128
#define NN    170
#define TT    12
#define XP    172   // padded pitch (multiple of 4 for float4)

#define SMEM1 ((2 * CH * XP + 32) * 4)                         // 176,256 B
#define SMEM2 (((NN * XP + 32) * 4) + (NN * NN * 2))           // 174,888 B

static __device__ float g_Ed[BATCH * NN * XP];   // E_d, [b][n][m] pitch XP
static __device__ float g_Asum[NN * NN];         // sum over batch of softmax

// ---------------------------------------------------------------- K0: zero
__global__ void k_zero_asum() {
    int i = blockIdx.x * blockDim.x + threadIdx.x;
    if (i < NN * NN) g_Asum[i] = 0.0f;
}

// ------------------------------------------------- K1: reduce_t + GEMM1 + tanh
// Per-batch CTA: xs[c][n] = sum_t x[b,c,n,t]; E_d[n][m] = tanh(sum_c xs*Es)
__global__ void __launch_bounds__(256, 1) k_embed(const float* __restrict__ x,
                                                  const float* __restrict__ Es) {
    extern __shared__ float sm[];
    float* xs = sm;                 // [CH][XP]
    float* es = sm + CH * XP;       // [CH][XP], +32 float slack after
    const int tid = threadIdx.x;
    const int b = blockIdx.x;

    // Phase 1: time reduction + E_s staging (coalesced 48B-per-thread reads)
    const float* xb = x + (size_t)b * (CH * NN * TT);
    for (int idx = tid; idx < CH * NN; idx += 256) {
        int c = idx / NN, n = idx - c * NN;
        const float4* p = reinterpret_cast<const float4*>(xb + (size_t)idx * TT);
        float4 v0 = p[0], v1 = p[1], v2 = p[2];
        float s = ((v0.x + v0.y) + (v0.z + v0.w))
                + ((v1.x + v1.y) + (v1.z + v1.w))
                + ((v2.x + v2.y) + (v2.z + v2.w));
        xs[c * XP + n] = s;
        es[c * XP + n] = Es[idx];   // Es is [CH][NN], same index space
    }
    // zero pad columns + tail slack (edge-tile overreads land here)
    for (int idx = tid; idx < CH * 2; idx += 256) {
        int c = idx >> 1, j = idx & 1;
        xs[c * XP + NN + j] = 0.0f;
        es[c * XP + NN + j] = 0.0f;
    }
    if (tid < 32) sm[2 * CH * XP + tid] = 0.0f;
    __syncthreads();

    // Phase 2: GEMM1. 16x16 threads, 4x4 register tile, 64x64 macro tiles (3x3)
    const int tx = tid & 15, ty = tid >> 4;
    float* Edb = g_Ed + (size_t)b * (NN * XP);

    for (int tn = 0; tn < 3; tn++) {
        for (int tm = 0; tm < 3; tm++) {
            const int an = tn * 64 + ty * 4;
            const int bm = tm * 64 + tx * 4;
            float acc[4][4];
            #pragma unroll
            for (int i = 0; i < 4; i++)
                #pragma unroll
                for (int j = 0; j < 4; j++) acc[i][j] = 0.0f;

            const float* ap = xs + an;
            const float* bp = es + bm;
            #pragma unroll 4
            for (int c = 0; c < CH; c++) {
                float4 a4 = *reinterpret_cast<const float4*>(ap + c * XP);
                float4 b4 = *reinterpret_cast<const float4*>(bp + c * XP);
                float av[4] = {a4.x, a4.y, a4.z, a4.w};
                float bv[4] = {b4.x, b4.y, b4.z, b4.w};
                #pragma unroll
                for (int i = 0; i < 4; i++)
                    #pragma unroll
                    for (int j = 0; j < 4; j++) acc[i][j] += av[i] * bv[j];
            }

            if (bm < NN) {   // bm multiple of 4 and <170 => bm+3 <= 171 fits pitch
                #pragma unroll
                for (int i = 0; i < 4; i++) {
                    int n = an + i;
                    if (n < NN) {
                        float4 v;
                        v.x = tanhf(acc[i][0]); v.y = tanhf(acc[i][1]);
                        v.z = tanhf(acc[i][2]); v.w = tanhf(acc[i][3]);
                        *reinterpret_cast<float4*>(Edb + n * XP + bm) = v;
                    }
                }
            }
        }
    }
}

// --------------------------------- K2: GEMM2 (symmetric) + softmax + accumulate
__global__ void __launch_bounds__(256, 1) k_adj() {
    extern __shared__ float sm[];
    float* ed = sm;  // [m][n] pitch XP (transposed E_d) + 32 float slack
    __nv_bfloat16* sc = reinterpret_cast<__nv_bfloat16*>(sm + NN * XP + 32); // [n][k]
    const int tid = threadIdx.x;
    const int b = blockIdx.x;
    const float* Edb = g_Ed + (size_t)b * (NN * XP);

    // transpose-load E_d into smem: coalesced global reads, strided STS
    for (int idx = tid; idx < NN * NN; idx += 256) {
        int n = idx / NN, m = idx - n * NN;
        ed[m * XP + n] = Edb[n * XP + m];
    }
    for (int idx = tid; idx < NN * 2; idx += 256) {
        int m = idx >> 1, j = idx & 1;
        ed[m * XP + NN + j] = 0.0f;
    }
    if (tid < 32) sm[NN * XP + tid] = 0.0f;
    __syncthreads();

    // GEMM2: scores = relu(Ed @ Ed^T / sqrt(C)); exploit symmetry: 6 of 9 tiles
    const int tx = tid & 15, ty = tid >> 4;
    const int n0s[6] = {0, 64, 128, 0, 0, 64};
    const int k0s[6] = {0, 64, 128, 64, 128, 128};

    for (int t = 0; t < 6; t++) {
        const int n0 = n0s[t], k0 = k0s[t];
        const int an = n0 + ty * 4;
        const int bk = k0 + tx * 4;
        float acc[4][4];
        #pragma unroll
        for (int i = 0; i < 4; i++)
            #pragma unroll
            for (int j = 0; j < 4; j++) acc[i][j] = 0.0f;

        const float* ap = ed + an;
        const float* bp = ed + bk;
        #pragma unroll 2
        for (int m = 0; m < NN; m++) {
            float4 a4 = *reinterpret_cast<const float4*>(ap + m * XP);
            float4 b4 = *reinterpret_cast<const float4*>(bp + m * XP);
            float av[4] = {a4.x, a4.y, a4.z, a4.w};
            float bv[4] = {b4.x, b4.y, b4.z, b4.w};
            #pragma unroll
            for (int i = 0; i < 4; i++)
                #pragma unroll
                for (int j = 0; j < 4; j++) acc[i][j] += av[i] * bv[j];
        }

        const float scale = 0.08838834764831843f;  // 1/sqrt(128)
        #pragma unroll
        for (int i = 0; i < 4; i++) {
            int n = an + i;
            if (n >= NN) continue;
            #pragma unroll
            for (int j = 0; j < 4; j++) {
                int k = bk + j;
                if (k >= NN) continue;
                float s = fmaxf(0.0f, acc[i][j] * scale);
                __nv_bfloat16 h = __float2bfloat16(s);
                sc[n * NN + k] = h;
                if (n0 != k0) sc[k * NN + n] = h;   // symmetric counterpart
            }
        }
    }
    __syncthreads();

    // Row softmax + atomic accumulation into g_Asum (one warp per row, strided)
    const int wid = tid >> 5, lane = tid & 31;
    for (int n = wid; n < NN; n += 8) {
        const __nv_bfloat16* row = sc + n * NN;
        float mx = -1e30f;
        for (int k = lane; k < NN; k += 32)
            mx = fmaxf(mx, __bfloat162float(row[k]));
        #pragma unroll
        for (int o = 16; o; o >>= 1)
            mx = fmaxf(mx, __shfl_xor_sync(0xffffffffu, mx, o));
        float ssum = 0.0f;
        for (int k = lane; k < NN; k += 32)
            ssum += __expf(__bfloat162float(row[k]) - mx);
        #pragma unroll
        for (int o = 16; o; o >>= 1)
            ssum += __shfl_xor_sync(0xffffffffu, ssum, o);
        float inv = 1.0f / ssum;
        for (int k = lane; k < NN; k += 32)
            atomicAdd(&g_Asum[n * NN + k],
                      __expf(__bfloat162float(row[k]) - mx) * inv);
    }
}

// ---------------------------------------------------------------- K3: threshold
__global__ void k_thresh(float* __restrict__ out) {
    int i = blockIdx.x * blockDim.x + threadIdx.x;
    if (i < NN * NN) out[i] = (g_Asum[i] > 64.0f) ? 1.0f : 0.0f;  // mean > 0.5
}

// ------------------------------------------------------------------- launcher
extern "C" void kernel_launch(void* const* d_in, const int* in_sizes, int n_in,
                              void* d_out, int out_size) {
    const float* x  = (const float*)d_in[0];   // [128,128,170,12] f32
    const float* Es = (const float*)d_in[1];   // [128,170] f32
    float* out = (float*)d_out;                // [170,170] f32

    cudaFuncSetAttribute(k_embed, cudaFuncAttributeMaxDynamicSharedMemorySize, SMEM1);
    cudaFuncSetAttribute(k_adj,   cudaFuncAttributeMaxDynamicSharedMemorySize, SMEM2);

    k_zero_asum<<<(NN * NN + 255) / 256, 256>>>();
    k_embed<<<BATCH, 256, SMEM1>>>(x, Es);
    k_adj<<<BATCH, 256, SMEM2>>>();
    k_thresh<<<(NN * NN + 255) / 256, 256>>>(out);
}

// round 3
// speedup vs baseline: 1.0629x; 1.0629x over previous
#include <cuda_runtime.h>
#include <cuda_bf16.h>
#include <cstdint>

#define BATCH 128
#define CH    128
#define NN    170
#define TT    12
#define XP    172   // padded pitch (multiple of 4 for float4/double2)

#define SMEM1 ((2 * CH * XP + 32) * 4)                         // 176,256 B
#define SMEM2 (((NN * XP + 32) * 4) + (NN * NN * 2))           // 174,888 B

static __device__ float g_Ed[BATCH * NN * XP];   // E_d, [b][n][m] pitch XP
static __device__ float g_Asum[NN * NN];         // sum over batch of softmax

// ------------------------------------------------------- packed f32x2 helpers
typedef unsigned long long u64t;

__device__ __forceinline__ u64t splat2(float v) {
    u64t d;
    asm("mov.b64 %0, {%1, %1};" : "=l"(d) : "f"(v));
    return d;
}
__device__ __forceinline__ void ffma2(u64t& c, u64t a, u64t b) {
    asm("fma.rn.f32x2 %0, %1, %2, %3;" : "=l"(c) : "l"(a), "l"(b), "l"(c));
}
__device__ __forceinline__ void unpack2(float& lo, float& hi, u64t v) {
    asm("mov.b64 {%0, %1}, %2;" : "=f"(lo), "=f"(hi) : "l"(v));
}

// ------------------------------------------------- K1: reduce_t + GEMM1 + tanh
// Per-batch CTA: xs[c][n] = sum_t x[b,c,n,t]; E_d[n][m] = tanh(sum_c xs*Es)
__global__ void __launch_bounds__(256, 1) k_embed(const float* __restrict__ x,
                                                  const float* __restrict__ Es) {
    extern __shared__ float sm[];
    float* xs = sm;                 // [CH][XP]
    float* es = sm + CH * XP;       // [CH][XP], +32 float slack after
    const int tid = threadIdx.x;
    const int b = blockIdx.x;

    // Phase 1: time reduction + E_s staging (coalesced 48B-per-thread reads)
    const float* xb = x + (size_t)b * (CH * NN * TT);
    for (int idx = tid; idx < CH * NN; idx += 256) {
        int c = idx / NN, n = idx - c * NN;
        const float4* p = reinterpret_cast<const float4*>(xb + (size_t)idx * TT);
        float4 v0 = p[0], v1 = p[1], v2 = p[2];
        float s = ((v0.x + v0.y) + (v0.z + v0.w))
                + ((v1.x + v1.y) + (v1.z + v1.w))
                + ((v2.x + v2.y) + (v2.z + v2.w));
        xs[c * XP + n] = s;
        es[c * XP + n] = Es[idx];   // Es is [CH][NN], same index space
    }
    // zero pad columns + tail slack (edge-tile overreads land here)
    for (int idx = tid; idx < CH * 2; idx += 256) {
        int c = idx >> 1, j = idx & 1;
        xs[c * XP + NN + j] = 0.0f;
        es[c * XP + NN + j] = 0.0f;
    }
    if (tid < 32) sm[2 * CH * XP + tid] = 0.0f;
    __syncthreads();

    // Phase 2: GEMM1. 16x16 threads, 4x4 register tile (packed f32x2 pairs),
    // 64x64 macro tiles (3x3)
    const int tx = tid & 15, ty = tid >> 4;
    float* Edb = g_Ed + (size_t)b * (NN * XP);

    for (int tn = 0; tn < 3; tn++) {
        for (int tm = 0; tm < 3; tm++) {
            const int an = tn * 64 + ty * 4;
            const int bm = tm * 64 + tx * 4;
            u64t acc[4][2];
            #pragma unroll
            for (int i = 0; i < 4; i++) { acc[i][0] = 0ull; acc[i][1] = 0ull; }

            const float* ap = xs + an;
            const float* bp = es + bm;
            #pragma unroll 4
            for (int c = 0; c < CH; c++) {
                float4 a4 = *reinterpret_cast<const float4*>(ap + c * XP);
                ulonglong2 b2 = *reinterpret_cast<const ulonglong2*>(bp + c * XP);
                u64t s0 = splat2(a4.x), s1 = splat2(a4.y),
                     s2 = splat2(a4.z), s3 = splat2(a4.w);
                ffma2(acc[0][0], s0, b2.x); ffma2(acc[0][1], s0, b2.y);
                ffma2(acc[1][0], s1, b2.x); ffma2(acc[1][1], s1, b2.y);
                ffma2(acc[2][0], s2, b2.x); ffma2(acc[2][1], s2, b2.y);
                ffma2(acc[3][0], s3, b2.x); ffma2(acc[3][1], s3, b2.y);
            }

            if (bm < NN) {   // bm multiple of 4 and <170 => bm+3 <= 171 fits pitch
                #pragma unroll
                for (int i = 0; i < 4; i++) {
                    int n = an + i;
                    if (n < NN) {
                        float a0, a1, a2, a3;
                        unpack2(a0, a1, acc[i][0]);
                        unpack2(a2, a3, acc[i][1]);
                        float4 v;
                        v.x = tanhf(a0); v.y = tanhf(a1);
                        v.z = tanhf(a2); v.w = tanhf(a3);
                        *reinterpret_cast<float4*>(Edb + n * XP + bm) = v;
                    }
                }
            }
        }
    }
}

// --------------------------------- K2: GEMM2 (symmetric) + softmax + accumulate
__global__ void __launch_bounds__(256, 1) k_adj() {
    extern __shared__ float sm[];
    float* ed = sm;  // [m][n] pitch XP (transposed E_d) + 32 float slack
    __nv_bfloat16* sc = reinterpret_cast<__nv_bfloat16*>(sm + NN * XP + 32); // [n][k]
    const int tid = threadIdx.x;
    const int b = blockIdx.x;
    const float* Edb = g_Ed + (size_t)b * (NN * XP);

    // transpose-load E_d into smem: coalesced global reads, strided STS
    for (int idx = tid; idx < NN * NN; idx += 256) {
        int n = idx / NN, m = idx - n * NN;
        ed[m * XP + n] = Edb[n * XP + m];
    }
    for (int idx = tid; idx < NN * 2; idx += 256) {
        int m = idx >> 1, j = idx & 1;
        ed[m * XP + NN + j] = 0.0f;
    }
    if (tid < 32) sm[NN * XP + tid] = 0.0f;
    __syncthreads();

    // GEMM2: scores = relu(Ed @ Ed^T / sqrt(C)); exploit symmetry: 6 of 9 tiles
    const int tx = tid & 15, ty = tid >> 4;
    const int n0s[6] = {0, 64, 128, 0, 0, 64};
    const int k0s[6] = {0, 64, 128, 64, 128, 128};

    for (int t = 0; t < 6; t++) {
        const int n0 = n0s[t], k0 = k0s[t];
        const int an = n0 + ty * 4;
        const int bk = k0 + tx * 4;
        u64t acc[4][2];
        #pragma unroll
        for (int i = 0; i < 4; i++) { acc[i][0] = 0ull; acc[i][1] = 0ull; }

        const float* ap = ed + an;
        const float* bp = ed + bk;
        #pragma unroll 2
        for (int m = 0; m < NN; m++) {
            float4 a4 = *reinterpret_cast<const float4*>(ap + m * XP);
            ulonglong2 b2 = *reinterpret_cast<const ulonglong2*>(bp + m * XP);
            u64t s0 = splat2(a4.x), s1 = splat2(a4.y),
                 s2 = splat2(a4.z), s3 = splat2(a4.w);
            ffma2(acc[0][0], s0, b2.x); ffma2(acc[0][1], s0, b2.y);
            ffma2(acc[1][0], s1, b2.x); ffma2(acc[1][1], s1, b2.y);
            ffma2(acc[2][0], s2, b2.x); ffma2(acc[2][1], s2, b2.y);
            ffma2(acc[3][0], s3, b2.x); ffma2(acc[3][1], s3, b2.y);
        }

        const float scale = 0.08838834764831843f;  // 1/sqrt(128)
        #pragma unroll
        for (int i = 0; i < 4; i++) {
            int n = an + i;
            if (n >= NN) continue;
            float av[4];
            unpack2(av[0], av[1], acc[i][0]);
            unpack2(av[2], av[3], acc[i][1]);
            #pragma unroll
            for (int j = 0; j < 4; j++) {
                int k = bk + j;
                if (k >= NN) continue;
                float s = fmaxf(0.0f, av[j] * scale);
                __nv_bfloat16 h = __float2bfloat16(s);
                sc[n * NN + k] = h;
                if (n0 != k0) sc[k * NN + n] = h;   // symmetric counterpart
            }
        }
    }
    __syncthreads();

    // Row softmax + atomic accumulation into g_Asum (one warp per row, strided)
    const int wid = tid >> 5, lane = tid & 31;
    for (int n = wid; n < NN; n += 8) {
        const __nv_bfloat16* row = sc + n * NN;
        float mx = -1e30f;
        for (int k = lane; k < NN; k += 32)
            mx = fmaxf(mx, __bfloat162float(row[k]));
        #pragma unroll
        for (int o = 16; o; o >>= 1)
            mx = fmaxf(mx, __shfl_xor_sync(0xffffffffu, mx, o));
        float ssum = 0.0f;
        for (int k = lane; k < NN; k += 32)
            ssum += __expf(__bfloat162float(row[k]) - mx);
        #pragma unroll
        for (int o = 16; o; o >>= 1)
            ssum += __shfl_xor_sync(0xffffffffu, ssum, o);
        float inv = 1.0f / ssum;
        for (int k = lane; k < NN; k += 32)
            atomicAdd(&g_Asum[n * NN + k],
                      __expf(__bfloat162float(row[k]) - mx) * inv);
    }
}

// --------------------------------- K3: threshold + self-restore (zero g_Asum)
__global__ void k_thresh(float* __restrict__ out) {
    int i = blockIdx.x * blockDim.x + threadIdx.x;
    if (i < NN * NN) {
        out[i] = (g_Asum[i] > 64.0f) ? 1.0f : 0.0f;  // mean > 0.5
        g_Asum[i] = 0.0f;  // restore for next (graph-replayed) run
    }
}

// ------------------------------------------------------------------- launcher
extern "C" void kernel_launch(void* const* d_in, const int* in_sizes, int n_in,
                              void* d_out, int out_size) {
    const float* x  = (const float*)d_in[0];   // [128,128,170,12] f32
    const float* Es = (const float*)d_in[1];   // [128,170] f32
    float* out = (float*)d_out;                // [170,170] f32

    cudaFuncSetAttribute(k_embed, cudaFuncAttributeMaxDynamicSharedMemorySize, SMEM1);
    cudaFuncSetAttribute(k_adj,   cudaFuncAttributeMaxDynamicSharedMemorySize, SMEM2);

    k_embed<<<BATCH, 256, SMEM1>>>(x, Es);
    k_adj<<<BATCH, 256, SMEM2>>>();
    k_thresh<<<(NN * NN + 255) / 256, 256>>>(out);
}

// round 4
// speedup vs baseline: 1.3292x; 1.2506x over previous
#include <cuda_runtime.h>
#include <cuda_bf16.h>
#include <cstdint>

#define BATCH 128
#define CH    128
#define NN    170
#define TT    12
#define XP    172   // padded pitch (multiple of 4 for float4/double2)

#define SMEM1 ((2 * CH * XP + 32) * 4)                         // 176,256 B
#define SMEM2 (((NN * XP + 32) * 4) + (NN * NN * 2))           // 174,888 B

static __device__ float g_Ed[BATCH * NN * XP];   // E_d, [b][n][m] pitch XP
static __device__ float g_Asum[NN * NN];         // sum over batch of softmax

// ------------------------------------------------------- packed f32x2 helpers
typedef unsigned long long u64t;

__device__ __forceinline__ u64t splat2(float v) {
    u64t d;
    asm("mov.b64 %0, {%1, %1};" : "=l"(d) : "f"(v));
    return d;
}
__device__ __forceinline__ void ffma2(u64t& c, u64t a, u64t b) {
    asm("fma.rn.f32x2 %0, %1, %2, %3;" : "=l"(c) : "l"(a), "l"(b), "l"(c));
}
__device__ __forceinline__ void unpack2(float& lo, float& hi, u64t v) {
    asm("mov.b64 {%0, %1}, %2;" : "=f"(lo), "=f"(hi) : "l"(v));
}

// ------------------------------------------------- K1: reduce_t + GEMM1 + tanh
// Per-batch CTA (512 thr): xs[c][n] = sum_t x[b,c,n,t]; Ed[n][m] = tanh(xs@Es)
__global__ void __launch_bounds__(512, 1) k_embed(const float* __restrict__ x,
                                                  const float* __restrict__ Es) {
    extern __shared__ float sm[];
    float* xs = sm;                 // [CH][XP]
    float* es = sm + CH * XP;       // [CH][XP], +32 float slack after
    const int tid = threadIdx.x;
    const int b = blockIdx.x;

    // Phase 1: time reduction + E_s staging (16 warps of load MLP)
    const float* xb = x + (size_t)b * (CH * NN * TT);
    for (int idx = tid; idx < CH * NN; idx += 512) {
        int c = idx / NN, n = idx - c * NN;
        const float4* p = reinterpret_cast<const float4*>(xb + (size_t)idx * TT);
        float4 v0 = p[0], v1 = p[1], v2 = p[2];
        float s = ((v0.x + v0.y) + (v0.z + v0.w))
                + ((v1.x + v1.y) + (v1.z + v1.w))
                + ((v2.x + v2.y) + (v2.z + v2.w));
        xs[c * XP + n] = s;
        es[c * XP + n] = Es[idx];
    }
    for (int idx = tid; idx < CH * 2; idx += 512) {
        int c = idx >> 1, j = idx & 1;
        xs[c * XP + NN + j] = 0.0f;
        es[c * XP + NN + j] = 0.0f;
    }
    if (tid < 32) sm[2 * CH * XP + tid] = 0.0f;
    __syncthreads();

    // Phase 2: GEMM1. Two 256-thread groups split the 9 macro tiles (5/4).
    const int grp = tid >> 8;
    const int gt  = tid & 255;
    const int tx = gt & 15, ty = gt >> 4;
    float* Edb = g_Ed + (size_t)b * (NN * XP);

    for (int t = grp; t < 9; t += 2) {
        const int tn = t / 3, tm = t - tn * 3;
        const int an = tn * 64 + ty * 4;
        const int bm = tm * 64 + tx * 4;
        u64t acc[4][2];
        #pragma unroll
        for (int i = 0; i < 4; i++) { acc[i][0] = 0ull; acc[i][1] = 0ull; }

        const float* ap = xs + an;
        const float* bp = es + bm;
        #pragma unroll 4
        for (int c = 0; c < CH; c++) {
            float4 a4 = *reinterpret_cast<const float4*>(ap + c * XP);
            ulonglong2 b2 = *reinterpret_cast<const ulonglong2*>(bp + c * XP);
            u64t s0 = splat2(a4.x), s1 = splat2(a4.y),
                 s2 = splat2(a4.z), s3 = splat2(a4.w);
            ffma2(acc[0][0], s0, b2.x); ffma2(acc[0][1], s0, b2.y);
            ffma2(acc[1][0], s1, b2.x); ffma2(acc[1][1], s1, b2.y);
            ffma2(acc[2][0], s2, b2.x); ffma2(acc[2][1], s2, b2.y);
            ffma2(acc[3][0], s3, b2.x); ffma2(acc[3][1], s3, b2.y);
        }

        if (bm < NN) {   // bm multiple of 4 and <170 => bm+3 <= 171 fits pitch
            #pragma unroll
            for (int i = 0; i < 4; i++) {
                int n = an + i;
                if (n < NN) {
                    float a0, a1, a2, a3;
                    unpack2(a0, a1, acc[i][0]);
                    unpack2(a2, a3, acc[i][1]);
                    float4 v;
                    v.x = tanhf(a0); v.y = tanhf(a1);
                    v.z = tanhf(a2); v.w = tanhf(a3);
                    *reinterpret_cast<float4*>(Edb + n * XP + bm) = v;
                }
            }
        }
    }
}

// --------------------------------- K2: GEMM2 (symmetric) + softmax + accumulate
__global__ void __launch_bounds__(512, 1) k_adj() {
    extern __shared__ float sm[];
    float* ed = sm;  // [m][n] pitch XP (transposed E_d) + 32 float slack
    __nv_bfloat16* sc = reinterpret_cast<__nv_bfloat16*>(sm + NN * XP + 32); // [n][k]
    const int tid = threadIdx.x;
    const int b = blockIdx.x;
    const float* Edb = g_Ed + (size_t)b * (NN * XP);

    // transpose-load E_d into smem: coalesced global reads, strided STS
    for (int idx = tid; idx < NN * NN; idx += 512) {
        int n = idx / NN, m = idx - n * NN;
        ed[m * XP + n] = Edb[n * XP + m];
    }
    for (int idx = tid; idx < NN * 2; idx += 512) {
        int m = idx >> 1, j = idx & 1;
        ed[m * XP + NN + j] = 0.0f;
    }
    if (tid < 32) sm[NN * XP + tid] = 0.0f;
    __syncthreads();

    // GEMM2: scores = relu(Ed @ Ed^T / sqrt(C)); symmetry: 6 of 9 tiles,
    // two 256-thread groups take 3 tiles each.
    const int grp = tid >> 8;
    const int gt  = tid & 255;
    const int tx = gt & 15, ty = gt >> 4;
    const int n0s[6] = {0, 64, 128, 0, 0, 64};
    const int k0s[6] = {0, 64, 128, 64, 128, 128};

    for (int t = grp; t < 6; t += 2) {
        const int n0 = n0s[t], k0 = k0s[t];
        const int an = n0 + ty * 4;
        const int bk = k0 + tx * 4;
        u64t acc[4][2];
        #pragma unroll
        for (int i = 0; i < 4; i++) { acc[i][0] = 0ull; acc[i][1] = 0ull; }

        const float* ap = ed + an;
        const float* bp = ed + bk;
        #pragma unroll 2
        for (int m = 0; m < NN; m++) {
            float4 a4 = *reinterpret_cast<const float4*>(ap + m * XP);
            ulonglong2 b2 = *reinterpret_cast<const ulonglong2*>(bp + m * XP);
            u64t s0 = splat2(a4.x), s1 = splat2(a4.y),
                 s2 = splat2(a4.z), s3 = splat2(a4.w);
            ffma2(acc[0][0], s0, b2.x); ffma2(acc[0][1], s0, b2.y);
            ffma2(acc[1][0], s1, b2.x); ffma2(acc[1][1], s1, b2.y);
            ffma2(acc[2][0], s2, b2.x); ffma2(acc[2][1], s2, b2.y);
            ffma2(acc[3][0], s3, b2.x); ffma2(acc[3][1], s3, b2.y);
        }

        const float scale = 0.08838834764831843f;  // 1/sqrt(128)
        #pragma unroll
        for (int i = 0; i < 4; i++) {
            int n = an + i;
            if (n >= NN) continue;
            float av[4];
            unpack2(av[0], av[1], acc[i][0]);
            unpack2(av[2], av[3], acc[i][1]);
            #pragma unroll
            for (int j = 0; j < 4; j++) {
                int k = bk + j;
                if (k >= NN) continue;
                float s = fmaxf(0.0f, av[j] * scale);
                __nv_bfloat16 h = __float2bfloat16(s);
                sc[n * NN + k] = h;
                if (n0 != k0) sc[k * NN + n] = h;   // symmetric counterpart
            }
        }
    }
    __syncthreads();

    // Row softmax + atomic accumulation (one warp per row, 16 warps strided)
    const int wid = tid >> 5, lane = tid & 31;
    for (int n = wid; n < NN; n += 16) {
        const __nv_bfloat16* row = sc + n * NN;
        float mx = -1e30f;
        for (int k = lane; k < NN; k += 32)
            mx = fmaxf(mx, __bfloat162float(row[k]));
        #pragma unroll
        for (int o = 16; o; o >>= 1)
            mx = fmaxf(mx, __shfl_xor_sync(0xffffffffu, mx, o));
        float ssum = 0.0f;
        for (int k = lane; k < NN; k += 32)
            ssum += __expf(__bfloat162float(row[k]) - mx);
        #pragma unroll
        for (int o = 16; o; o >>= 1)
            ssum += __shfl_xor_sync(0xffffffffu, ssum, o);
        float inv = 1.0f / ssum;
        for (int k = lane; k < NN; k += 32)
            atomicAdd(&g_Asum[n * NN + k],
                      __expf(__bfloat162float(row[k]) - mx) * inv);
    }
}

// --------------------------------- K3: threshold + self-restore (zero g_Asum)
__global__ void k_thresh(float* __restrict__ out) {
    int i = blockIdx.x * blockDim.x + threadIdx.x;
    if (i < NN * NN) {
        out[i] = (g_Asum[i] > 64.0f) ? 1.0f : 0.0f;  // mean > 0.5
        g_Asum[i] = 0.0f;  // restore for next (graph-replayed) run
    }
}

// ------------------------------------------------------------------- launcher
extern "C" void kernel_launch(void* const* d_in, const int* in_sizes, int n_in,
                              void* d_out, int out_size) {
    const float* x  = (const float*)d_in[0];   // [128,128,170,12] f32
    const float* Es = (const float*)d_in[1];   // [128,170] f32
    float* out = (float*)d_out;                // [170,170] f32

    cudaFuncSetAttribute(k_embed, cudaFuncAttributeMaxDynamicSharedMemorySize, SMEM1);
    cudaFuncSetAttribute(k_adj,   cudaFuncAttributeMaxDynamicSharedMemorySize, SMEM2);

    k_embed<<<BATCH, 512, SMEM1>>>(x, Es);
    k_adj<<<BATCH, 512, SMEM2>>>();
    k_thresh<<<(NN * NN + 255) / 256, 256>>>(out);
}